// round 15
// baseline (speedup 1.0000x reference)
#include <cuda_runtime.h>
#include <cuda_fp16.h>
#include <cstdint>

#define DIN   128
#define HID   256
#define LAT   64
#define NMAX  50000
#define E_BLK 128          // edges per edge-CTA (256 thr, 8 warps x 16 rows)

// ---------- static device buffers ----------
__device__ __align__(16) __half g_w1s[4 * 128 * 136];   // W1 staged [ch][k128][136]
__device__ __align__(16) __half g_w2s[256 * 72];        // W2 k-row + n-col permuted [256][72]
__device__ __align__(16) __half g_U  [NMAX * HID];      // x@W1a + b1
__device__ __align__(16) __half g_V  [NMAX * HID];      // x@W1b

// ---------- node kernel smem ----------
#define PA_ST   272
#define PAS_OFF 0
#define PWB_OFF (128 * PA_ST)
#define PW_ST   272
#define PB1_OFF (PWB_OFF + 2 * 128 * PW_ST)
#define PMB_OFF (PB1_OFF + 1024)
#define P_SMEM  105600

// ---------- edge kernel smem (warp-private cp.async stages) ----------
// per warp: 2 buffers x (16 U rows + 16 V rows) x 64B = 2 x 2048
#define WARP_AREA 4096
#define STG_OFF  0
#define W2_OFF   (8 * WARP_AREA)        // 32768
#define W2_ST    144
#define EB2_OFF  (W2_OFF + 256 * W2_ST) // 69632 (64 f32)
#define ESI_OFF  (EB2_OFF + 256)        // 69888 (256 int)
#define EMB_OFF  (ESI_OFF + 1024)       // 70912
#define EFL_OFF  (EMB_OFF + 8)
#define E_SMEM   71040                  // x3 CTAs = 213 KB <= 228 KB

// ---------------- helpers ----------------
__device__ __forceinline__ uint32_t smem_u32(const void* p) {
    uint32_t a;
    asm("{ .reg .u64 t; cvta.to.shared.u64 t, %1; cvt.u32.u64 %0, t; }" : "=r"(a) : "l"(p));
    return a;
}
__device__ __forceinline__ void mma16(float c[4], const uint32_t a[4],
                                      uint32_t b0, uint32_t b1) {
    asm volatile("mma.sync.aligned.m16n8k16.row.col.f32.f16.f16.f32 "
        "{%0,%1,%2,%3}, {%4,%5,%6,%7}, {%8,%9}, {%0,%1,%2,%3};"
        : "+f"(c[0]), "+f"(c[1]), "+f"(c[2]), "+f"(c[3])
        : "r"(a[0]), "r"(a[1]), "r"(a[2]), "r"(a[3]), "r"(b0), "r"(b1));
}
__device__ __forceinline__ void ldsm4(uint32_t r[4], uint32_t addr) {
    asm volatile("ldmatrix.sync.aligned.m8n8.x4.shared.b16 {%0,%1,%2,%3}, [%4];"
        : "=r"(r[0]), "=r"(r[1]), "=r"(r[2]), "=r"(r[3]) : "r"(addr));
}
__device__ __forceinline__ void ldsm4t(uint32_t r[4], uint32_t addr) {
    asm volatile("ldmatrix.sync.aligned.m8n8.x4.trans.shared.b16 {%0,%1,%2,%3}, [%4];"
        : "=r"(r[0]), "=r"(r[1]), "=r"(r[2]), "=r"(r[3]) : "r"(addr));
}
__device__ __forceinline__ void mbar_init(uint32_t a, uint32_t cnt) {
    asm volatile("mbarrier.init.shared.b64 [%0], %1;" :: "r"(a), "r"(cnt) : "memory");
}
__device__ __forceinline__ void mbar_wait(uint32_t a, uint32_t parity) {
    asm volatile(
        "{\n\t.reg .pred P;\n\t"
        "WL_%=:\n\t"
        "mbarrier.try_wait.parity.acquire.cta.shared::cta.b64 P, [%0], %1, 0x989680;\n\t"
        "@P bra.uni WD_%=;\n\t"
        "bra.uni WL_%=;\n\t"
        "WD_%=:\n\t}"
        :: "r"(a), "r"(parity) : "memory");
}
__device__ __forceinline__ void bulk_in(uint32_t dst, const void* src, uint32_t bytes,
                                        uint32_t mbar) {
    asm volatile("mbarrier.arrive.expect_tx.shared.b64 _, [%0], %1;"
                 :: "r"(mbar), "r"(bytes) : "memory");
    asm volatile("cp.async.bulk.shared::cta.global.mbarrier::complete_tx::bytes "
                 "[%0], [%1], %2, [%3];"
                 :: "r"(dst), "l"(src), "r"(bytes), "r"(mbar) : "memory");
}
__device__ __forceinline__ void cp_async16(uint32_t dst, const void* src) {
    asm volatile("cp.async.ca.shared.global [%0], [%1], 16;" :: "r"(dst), "l"(src) : "memory");
}
__device__ __forceinline__ uint32_t relu2(uint32_t u, uint32_t v) {
    __half2 r = __hmax2(__hadd2(*(__half2*)&u, *(__half2*)&v), __float2half2_rn(0.f));
    return *(uint32_t*)&r;
}

// ---------------- prep: weights (W2 k-row + store-coalescing n-col permutation) ----
__global__ void prep_kernel(const float* __restrict__ W1,
                            const float* __restrict__ W2)
{
    const int stride = gridDim.x * blockDim.x;
    int gtid = blockIdx.x * blockDim.x + threadIdx.x;
    for (int i = gtid; i < 4 * 128 * 136; i += stride) {
        const int ch = i / (128 * 136);
        const int r  = i % (128 * 136);
        const int k  = r / 136;
        const int n  = r % 136;
        float val = 0.f;
        if (n < 128)
            val = W1[(size_t)((ch < 2 ? 0 : 128) + k) * HID + (ch & 1) * 128 + n];
        g_w1s[i] = __float2half_rn(val);
    }
    for (int i = gtid; i < 256 * 72; i += stride) {
        const int r = i / 72, m = i % 72;
        float val = 0.f;
        if (m < 64) {
            const int c   = r >> 5;
            const int rem = r & 31;
            const int j   = rem >> 4;
            const int l   = rem & 15;
            const int q   = (l & 7) >> 1;
            const int dlt = l & 1;
            const int hi  = l >> 3;
            const int p   = 32 * c + 8 * q + 4 * j + 2 * hi + dlt;       // physical k row
            const int srcc = 16 * (m >> 4) + 4 * ((m & 7) >> 1)
                           + 2 * ((m >> 3) & 1) + (m & 1);               // physical col
            val = W2[(size_t)p * LAT + srcc];
        }
        g_w2s[i] = __float2half_rn(val);
    }
}

// ---------------- node kernel: U = x@W1a + b1, V = x@W1b ----------------
__global__ __launch_bounds__(256, 2)
void node_kernel(const float* __restrict__ x,
                 const float* __restrict__ b1, int n_nodes)
{
    extern __shared__ char sm[];
    const uint32_t sb = smem_u32(sm);
    float* b1s = (float*)(sm + PB1_OFF);

    const int tid  = threadIdx.x;
    const int lane = tid & 31;
    const int warp = tid >> 5;
    const int wM   = warp & 3;
    const int wN   = warp >> 2;
    const int g    = lane >> 2;
    const int t4   = lane & 3;
    const int n0   = blockIdx.x * 128;

    const int lrow  = lane & 15;
    const int lkoff = (lane >> 4) * 16;
    const int bkrow = (lane & 7) + ((lane >> 3) & 1) * 8;
    const int bnoff = ((lane >> 4) & 1) * 16;

    if (tid == 0) {
        mbar_init(sb + PMB_OFF, 1);
        mbar_init(sb + PMB_OFF + 8, 1);
        asm volatile("fence.proxy.async.shared::cta;" ::: "memory");
        bulk_in(sb + PWB_OFF,               g_w1s,             128 * PW_ST, sb + PMB_OFF);
        bulk_in(sb + PWB_OFF + 128 * PW_ST, g_w1s + 128 * 136, 128 * PW_ST, sb + PMB_OFF + 8);
    }
    b1s[tid] = b1[tid];

    #pragma unroll
    for (int j = 0; j < 16; j++) {
        int i = tid + j * 256;
        int r = i >> 5;
        int ch = i & 31;
        int node = n0 + r; if (node >= n_nodes) node = n_nodes - 1;
        float4 v = *(const float4*)(x + (size_t)node * DIN + ch * 4);
        __half2 h0 = __floats2half2_rn(v.x, v.y);
        __half2 h1 = __floats2half2_rn(v.z, v.w);
        uint2 u;
        u.x = *(uint32_t*)&h0;
        u.y = *(uint32_t*)&h1;
        *(uint2*)(sm + PAS_OFF + r * PA_ST + ch * 8) = u;
    }
    __syncthreads();

    #pragma unroll 1
    for (int ch = 0; ch < 4; ch++) {
        const int buf = ch & 1;
        mbar_wait(sb + PMB_OFF + buf * 8, (uint32_t)((ch >> 1) & 1));
        const uint32_t wb = sb + (uint32_t)(PWB_OFF + buf * 128 * PW_ST);

        float acc[2][8][4];
        #pragma unroll
        for (int mt = 0; mt < 2; mt++)
            #pragma unroll
            for (int nt = 0; nt < 8; nt++)
                #pragma unroll
                for (int q = 0; q < 4; q++) acc[mt][nt][q] = 0.f;

        #pragma unroll
        for (int kk = 0; kk < 8; kk++) {
            const int kh = kk * 16;
            uint32_t a[2][4];
            const uint32_t abase = sb + PAS_OFF + (uint32_t)((wM * 32 + lrow) * PA_ST)
                                 + (uint32_t)(kh * 2 + lkoff);
            ldsm4(a[0], abase);
            ldsm4(a[1], abase + (uint32_t)(16 * PA_ST));

            uint32_t bf[4][4];
            const uint32_t bbase = wb + (uint32_t)((kh + bkrow) * PW_ST)
                                 + (uint32_t)(wN * 128 + bnoff);
            #pragma unroll
            for (int q = 0; q < 4; q++) ldsm4t(bf[q], bbase + (uint32_t)(q * 32));

            #pragma unroll
            for (int q = 0; q < 4; q++)
                #pragma unroll
                for (int h = 0; h < 2; h++) {
                    const int nt = q * 2 + h;
                    mma16(acc[0][nt], a[0], bf[q][h * 2], bf[q][h * 2 + 1]);
                    mma16(acc[1][nt], a[1], bf[q][h * 2], bf[q][h * 2 + 1]);
                }
        }

        __half* dst = (ch < 2) ? g_U : g_V;
        const bool isU = (ch < 2);
        #pragma unroll
        for (int mt = 0; mt < 2; mt++) {
            const int nd0 = n0 + wM * 32 + mt * 16 + g;
            #pragma unroll
            for (int nt = 0; nt < 8; nt++) {
                const int c = wN * 64 + nt * 8 + (t4 << 1);
                const int gc = (ch & 1) * 128 + c;
                const float bx = isU ? b1s[gc]     : 0.f;
                const float by = isU ? b1s[gc + 1] : 0.f;
                if (nd0 < n_nodes)
                    *(__half2*)(dst + (size_t)nd0 * HID + gc) =
                        __floats2half2_rn(acc[mt][nt][0] + bx, acc[mt][nt][1] + by);
                if (nd0 + 8 < n_nodes)
                    *(__half2*)(dst + (size_t)(nd0 + 8) * HID + gc) =
                        __floats2half2_rn(acc[mt][nt][2] + bx, acc[mt][nt][3] + by);
            }
        }
        __syncthreads();
        if (tid == 0 && ch + 2 < 4)
            bulk_in(sb + (uint32_t)(PWB_OFF + buf * 128 * PW_ST),
                    g_w1s + (size_t)(ch + 2) * 128 * 136, 128 * PW_ST,
                    sb + PMB_OFF + buf * 8);
    }
}

// ---------------- edge kernel: cp.async warp-private stages, 3 CTAs/SM ----------------
__global__ __launch_bounds__(256, 3)
void edge_kernel(const void*  __restrict__ ei_raw,
                 const float* __restrict__ b2,
                 float* __restrict__ out,
                 int E, int n_nodes)
{
    extern __shared__ char sm[];
    const uint32_t sb = smem_u32(sm);
    float* b2s = (float*)(sm + EB2_OFF);
    int*   sidx = (int*)(sm + ESI_OFF);

    const int tid  = threadIdx.x;
    const int lane = tid & 31;
    const int warp = tid >> 5;            // 8 warps x 16 edge rows
    const int q    = lane & 3;
    const int e0   = blockIdx.x * E_BLK;
    const int nmax = (n_nodes < NMAX ? n_nodes : NMAX) - 1;

    const int bkrow = (lane & 7) + ((lane >> 3) & 1) * 8;
    const int bnoff = ((lane >> 4) & 1) * 16;

    if (tid == 0) {
        mbar_init(sb + EMB_OFF, 1);
        asm volatile("fence.proxy.async.shared::cta;" ::: "memory");
        bulk_in(sb + W2_OFF, g_w2s, 256 * W2_ST, sb + EMB_OFF);
        const int* e32 = (const int*)ei_raw;
        int hi0 = 1;
        #pragma unroll
        for (int k = 0; k < 16; k++) hi0 &= (e32[2 * k + 1] == 0);
        *(int*)(sm + EFL_OFF) = hi0;
    }
    __syncthreads();
    const bool is64 = (*(int*)(sm + EFL_OFF) != 0);

    if (tid < 2 * E_BLK) {
        int which = tid >= E_BLK;
        int r = tid - which * E_BLK;
        int e = e0 + r; if (e >= E) e = E - 1;
        long long v;
        if (is64) v = ((const long long*)ei_raw)[(size_t)which * E + e];
        else      v = ((const int*)ei_raw)[(size_t)which * E + e];
        int vi = (int)v;
        if (vi < 0) vi = 0;
        if (vi > nmax) vi = nmax;
        sidx[which * E_BLK + r] = vi;
    }
    if (tid < LAT) b2s[tid] = b2[tid];
    __syncthreads();

    // per-lane gather assignment: lanes 0-15 -> U rows 0-15, lanes 16-31 -> V rows 0-15
    const int crow = lane & 15;
    const int carr = lane >> 4;
    const int cnode = carr ? sidx[E_BLK + warp * 16 + crow] : sidx[warp * 16 + crow];
    const __half* csrc = (carr ? g_V : g_U) + (size_t)cnode * HID;
    const uint32_t cdst = sb + (uint32_t)(STG_OFF + warp * WARP_AREA + carr * 1024 + crow * 64);

    // compute rows (same as R14)
    const int lrA = lane >> 2;            // 0..7
    const int rA  = warp * 16 + lrA;
    const int rB  = rA + 8;
    const uint32_t wsbase = sb + (uint32_t)(STG_OFF + warp * WARP_AREA);

    float acc[8][4];
    #pragma unroll
    for (int nt = 0; nt < 8; nt++)
        #pragma unroll
        for (int c = 0; c < 4; c++) acc[nt][c] = 0.f;

    // prologue: stage chunks 0 and 1
    #pragma unroll
    for (int cc = 0; cc < 2; cc++) {
        #pragma unroll
        for (int i = 0; i < 4; i++)
            cp_async16(cdst + (uint32_t)(cc * 2048 + i * 16), csrc + cc * 32 + i * 8);
        asm volatile("cp.async.commit_group;" ::: "memory");
    }

    mbar_wait(sb + EMB_OFF, 0);           // W2 resident

    #pragma unroll
    for (int c = 0; c < 8; c++) {
        asm volatile("cp.async.wait_group 1;" ::: "memory");
        __syncwarp();

        const uint32_t stg = wsbase + (uint32_t)((c & 1) * 2048);
        const char* stgp = sm + (stg - sb);
        uint4 uA = *(const uint4*)(stgp + lrA * 64 + q * 16);
        uint4 uB = *(const uint4*)(stgp + (lrA + 8) * 64 + q * 16);
        uint4 vA = *(const uint4*)(stgp + 1024 + lrA * 64 + q * 16);
        uint4 vB = *(const uint4*)(stgp + 1024 + (lrA + 8) * 64 + q * 16);
        __syncwarp();                     // all lanes done reading this buffer

        // refill this buffer with chunk c+2 (flies under the MMAs below)
        if (c + 2 < 8) {
            #pragma unroll
            for (int i = 0; i < 4; i++)
                cp_async16(cdst + (uint32_t)((c & 1) * 2048 + i * 16),
                           csrc + (c + 2) * 32 + i * 8);
        }
        asm volatile("cp.async.commit_group;" ::: "memory");   // always (keeps count)

        uint32_t hA[4], hB[4];
        const uint32_t* ua = (const uint32_t*)&uA;
        const uint32_t* ub = (const uint32_t*)&uB;
        const uint32_t* va = (const uint32_t*)&vA;
        const uint32_t* vb = (const uint32_t*)&vB;
        #pragma unroll
        for (int r = 0; r < 4; r++) {
            hA[r] = relu2(ua[r], va[r]);
            hB[r] = relu2(ub[r], vb[r]);
        }
        #pragma unroll
        for (int j = 0; j < 2; j++) {
            uint32_t a[4] = { hA[j * 2], hB[j * 2], hA[j * 2 + 1], hB[j * 2 + 1] };
            const uint32_t bbase = sb + W2_OFF
                                 + (uint32_t)((c * 32 + j * 16 + bkrow) * W2_ST)
                                 + (uint32_t)bnoff;
            #pragma unroll
            for (int qq = 0; qq < 4; qq++) {
                uint32_t bf[4];
                ldsm4t(bf, bbase + (uint32_t)(qq * 32));
                mma16(acc[qq * 2 + 0], a, bf[0], bf[1]);
                mma16(acc[qq * 2 + 1], a, bf[2], bf[3]);
            }
        }
    }

    // epilogue: acc[nt][h] physical col = 16*(nt>>1) + 4q + 2*(nt&1) + h
    const int eA = e0 + rA;
    const int eB = e0 + rB;
    #pragma unroll
    for (int m = 0; m < 4; m++) {
        const int cbase = 16 * m + 4 * q;
        float4 bv = *(const float4*)(b2s + cbase);
        if (eA < E) {
            float4 o;
            o.x = acc[2 * m][0] + bv.x;     o.y = acc[2 * m][1] + bv.y;
            o.z = acc[2 * m + 1][0] + bv.z; o.w = acc[2 * m + 1][1] + bv.w;
            *(float4*)(out + (size_t)eA * LAT + cbase) = o;
        }
        if (eB < E) {
            float4 o;
            o.x = acc[2 * m][2] + bv.x;     o.y = acc[2 * m][3] + bv.y;
            o.z = acc[2 * m + 1][2] + bv.z; o.w = acc[2 * m + 1][3] + bv.w;
            *(float4*)(out + (size_t)eB * LAT + cbase) = o;
        }
    }
}

extern "C" void kernel_launch(void* const* d_in, const int* in_sizes, int n_in,
                              void* d_out, int out_size) {
    int ix = -1, ie = -1, iw1 = -1, ib1 = -1, iw2 = -1, ib2 = -1;
    for (int i = 0; i < n_in; i++) {
        switch (in_sizes[i]) {
            case 50000 * 128:  ix  = i; break;
            case 2 * 600000:   ie  = i; break;
            case 256 * 256:    iw1 = i; break;
            case 256:          ib1 = i; break;
            case 256 * 64:     iw2 = i; break;
            case 64:           ib2 = i; break;
            default: break;
        }
    }
    if (ix < 0)  ix = 0;
    if (ie < 0)  ie = 1;
    if (iw1 < 0) iw1 = 2;
    if (ib1 < 0) ib1 = 3;
    if (iw2 < 0) iw2 = 4;
    if (ib2 < 0) ib2 = 5;

    const float* x  = (const float*)d_in[ix];
    const void*  ei = (const void*)d_in[ie];
    const float* W1 = (const float*)d_in[iw1];
    const float* b1 = (const float*)d_in[ib1];
    const float* W2 = (const float*)d_in[iw2];
    const float* b2 = (const float*)d_in[ib2];
    float* out = (float*)d_out;

    const int E = in_sizes[ie] / 2;
    int n_nodes = in_sizes[ix] / DIN;
    if (n_nodes > NMAX) n_nodes = NMAX;

    prep_kernel<<<512, 256>>>(W1, W2);

    cudaFuncSetAttribute(node_kernel,
                         cudaFuncAttributeMaxDynamicSharedMemorySize, P_SMEM);
    node_kernel<<<(n_nodes + 127) / 128, 256, P_SMEM>>>(x, b1, n_nodes);

    cudaFuncSetAttribute(edge_kernel,
                         cudaFuncAttributeMaxDynamicSharedMemorySize, E_SMEM);
    edge_kernel<<<(E + E_BLK - 1) / E_BLK, 256, E_SMEM>>>(ei, b2, out, E, n_nodes);
}

// round 16
// speedup vs baseline: 1.9149x; 1.9149x over previous
#include <cuda_runtime.h>
#include <cuda_fp16.h>
#include <cstdint>

#define DIN   128
#define HID   256
#define LAT   64
#define NMAX  50000
#define E_BLK 256          // edges per edge-CTA (512 thr, 16 warps x 16 rows)

// ---------- static device buffers ----------
__device__ __align__(16) __half g_w1s[4 * 128 * 136];   // W1 staged [ch][k128][136]
__device__ __align__(16) __half g_w2s[256 * 72];        // W2 k-row + n-col permuted [256][72]
__device__ __align__(16) __half g_U  [NMAX * HID];      // x@W1a + b1
__device__ __align__(16) __half g_V  [NMAX * HID];      // x@W1b

// ---------- node kernel smem ----------
#define PA_ST   272
#define PAS_OFF 0
#define PWB_OFF (128 * PA_ST)
#define PW_ST   272
#define PB1_OFF (PWB_OFF + 2 * 128 * PW_ST)
#define PMB_OFF (PB1_OFF + 1024)
#define P_SMEM  105600

// ---------- edge kernel smem ----------
#define W2_OFF  0
#define W2_ST   144
#define EB2_OFF (256 * W2_ST)          // 36864 (64 f32)
#define ESI_OFF (EB2_OFF + 256)        // 37120 (512 int)
#define EMB_OFF (ESI_OFF + 2048)       // 39168
#define EFL_OFF (EMB_OFF + 8)
#define E_SMEM  39424

// ---------------- helpers ----------------
__device__ __forceinline__ uint32_t smem_u32(const void* p) {
    uint32_t a;
    asm("{ .reg .u64 t; cvta.to.shared.u64 t, %1; cvt.u32.u64 %0, t; }" : "=r"(a) : "l"(p));
    return a;
}
__device__ __forceinline__ void mma16(float c[4], const uint32_t a[4],
                                      uint32_t b0, uint32_t b1) {
    asm volatile("mma.sync.aligned.m16n8k16.row.col.f32.f16.f16.f32 "
        "{%0,%1,%2,%3}, {%4,%5,%6,%7}, {%8,%9}, {%0,%1,%2,%3};"
        : "+f"(c[0]), "+f"(c[1]), "+f"(c[2]), "+f"(c[3])
        : "r"(a[0]), "r"(a[1]), "r"(a[2]), "r"(a[3]), "r"(b0), "r"(b1));
}
__device__ __forceinline__ void ldsm4(uint32_t r[4], uint32_t addr) {
    asm volatile("ldmatrix.sync.aligned.m8n8.x4.shared.b16 {%0,%1,%2,%3}, [%4];"
        : "=r"(r[0]), "=r"(r[1]), "=r"(r[2]), "=r"(r[3]) : "r"(addr));
}
__device__ __forceinline__ void ldsm4t(uint32_t r[4], uint32_t addr) {
    asm volatile("ldmatrix.sync.aligned.m8n8.x4.trans.shared.b16 {%0,%1,%2,%3}, [%4];"
        : "=r"(r[0]), "=r"(r[1]), "=r"(r[2]), "=r"(r[3]) : "r"(addr));
}
__device__ __forceinline__ void mbar_init(uint32_t a, uint32_t cnt) {
    asm volatile("mbarrier.init.shared.b64 [%0], %1;" :: "r"(a), "r"(cnt) : "memory");
}
__device__ __forceinline__ void mbar_wait(uint32_t a, uint32_t parity) {
    asm volatile(
        "{\n\t.reg .pred P;\n\t"
        "WL_%=:\n\t"
        "mbarrier.try_wait.parity.acquire.cta.shared::cta.b64 P, [%0], %1, 0x989680;\n\t"
        "@P bra.uni WD_%=;\n\t"
        "bra.uni WL_%=;\n\t"
        "WD_%=:\n\t}"
        :: "r"(a), "r"(parity) : "memory");
}
__device__ __forceinline__ void bulk_in(uint32_t dst, const void* src, uint32_t bytes,
                                        uint32_t mbar) {
    asm volatile("mbarrier.arrive.expect_tx.shared.b64 _, [%0], %1;"
                 :: "r"(mbar), "r"(bytes) : "memory");
    asm volatile("cp.async.bulk.shared::cta.global.mbarrier::complete_tx::bytes "
                 "[%0], [%1], %2, [%3];"
                 :: "r"(dst), "l"(src), "r"(bytes), "r"(mbar) : "memory");
}
__device__ __forceinline__ uint32_t relu2(uint32_t u, uint32_t v) {
    __half2 r = __hmax2(__hadd2(*(__half2*)&u, *(__half2*)&v), __float2half2_rn(0.f));
    return *(uint32_t*)&r;
}
__device__ __forceinline__ uint4 ldg_nc16(const __half* p) {
    uint4 v;
    asm volatile("ld.global.nc.v4.u32 {%0,%1,%2,%3}, [%4];"
        : "=r"(v.x), "=r"(v.y), "=r"(v.z), "=r"(v.w) : "l"(p));
    return v;
}

// ---------------- prep: weights (W2 k-row + store-coalescing n-col permutation) ----
__global__ void prep_kernel(const float* __restrict__ W1,
                            const float* __restrict__ W2)
{
    const int stride = gridDim.x * blockDim.x;
    int gtid = blockIdx.x * blockDim.x + threadIdx.x;
    for (int i = gtid; i < 4 * 128 * 136; i += stride) {
        const int ch = i / (128 * 136);
        const int r  = i % (128 * 136);
        const int k  = r / 136;
        const int n  = r % 136;
        float val = 0.f;
        if (n < 128)
            val = W1[(size_t)((ch < 2 ? 0 : 128) + k) * HID + (ch & 1) * 128 + n];
        g_w1s[i] = __float2half_rn(val);
    }
    for (int i = gtid; i < 256 * 72; i += stride) {
        const int r = i / 72, m = i % 72;
        float val = 0.f;
        if (m < 64) {
            const int c   = r >> 5;
            const int rem = r & 31;
            const int j   = rem >> 4;
            const int l   = rem & 15;
            const int q   = (l & 7) >> 1;
            const int dlt = l & 1;
            const int hi  = l >> 3;
            const int p   = 32 * c + 8 * q + 4 * j + 2 * hi + dlt;       // physical k row
            const int srcc = 16 * (m >> 4) + 4 * ((m & 7) >> 1)
                           + 2 * ((m >> 3) & 1) + (m & 1);               // physical col
            val = W2[(size_t)p * LAT + srcc];
        }
        g_w2s[i] = __float2half_rn(val);
    }
}

// ---------------- node kernel: U = x@W1a + b1, V = x@W1b ----------------
__global__ __launch_bounds__(256, 2)
void node_kernel(const float* __restrict__ x,
                 const float* __restrict__ b1, int n_nodes)
{
    extern __shared__ char sm[];
    const uint32_t sb = smem_u32(sm);
    float* b1s = (float*)(sm + PB1_OFF);

    const int tid  = threadIdx.x;
    const int lane = tid & 31;
    const int warp = tid >> 5;
    const int wM   = warp & 3;
    const int wN   = warp >> 2;
    const int g    = lane >> 2;
    const int t4   = lane & 3;
    const int n0   = blockIdx.x * 128;

    const int lrow  = lane & 15;
    const int lkoff = (lane >> 4) * 16;
    const int bkrow = (lane & 7) + ((lane >> 3) & 1) * 8;
    const int bnoff = ((lane >> 4) & 1) * 16;

    if (tid == 0) {
        mbar_init(sb + PMB_OFF, 1);
        mbar_init(sb + PMB_OFF + 8, 1);
        asm volatile("fence.proxy.async.shared::cta;" ::: "memory");
        bulk_in(sb + PWB_OFF,               g_w1s,             128 * PW_ST, sb + PMB_OFF);
        bulk_in(sb + PWB_OFF + 128 * PW_ST, g_w1s + 128 * 136, 128 * PW_ST, sb + PMB_OFF + 8);
    }
    b1s[tid] = b1[tid];

    #pragma unroll
    for (int j = 0; j < 16; j++) {
        int i = tid + j * 256;
        int r = i >> 5;
        int ch = i & 31;
        int node = n0 + r; if (node >= n_nodes) node = n_nodes - 1;
        float4 v = *(const float4*)(x + (size_t)node * DIN + ch * 4);
        __half2 h0 = __floats2half2_rn(v.x, v.y);
        __half2 h1 = __floats2half2_rn(v.z, v.w);
        uint2 u;
        u.x = *(uint32_t*)&h0;
        u.y = *(uint32_t*)&h1;
        *(uint2*)(sm + PAS_OFF + r * PA_ST + ch * 8) = u;
    }
    __syncthreads();

    #pragma unroll 1
    for (int ch = 0; ch < 4; ch++) {
        const int buf = ch & 1;
        mbar_wait(sb + PMB_OFF + buf * 8, (uint32_t)((ch >> 1) & 1));
        const uint32_t wb = sb + (uint32_t)(PWB_OFF + buf * 128 * PW_ST);

        float acc[2][8][4];
        #pragma unroll
        for (int mt = 0; mt < 2; mt++)
            #pragma unroll
            for (int nt = 0; nt < 8; nt++)
                #pragma unroll
                for (int q = 0; q < 4; q++) acc[mt][nt][q] = 0.f;

        #pragma unroll
        for (int kk = 0; kk < 8; kk++) {
            const int kh = kk * 16;
            uint32_t a[2][4];
            const uint32_t abase = sb + PAS_OFF + (uint32_t)((wM * 32 + lrow) * PA_ST)
                                 + (uint32_t)(kh * 2 + lkoff);
            ldsm4(a[0], abase);
            ldsm4(a[1], abase + (uint32_t)(16 * PA_ST));

            uint32_t bf[4][4];
            const uint32_t bbase = wb + (uint32_t)((kh + bkrow) * PW_ST)
                                 + (uint32_t)(wN * 128 + bnoff);
            #pragma unroll
            for (int q = 0; q < 4; q++) ldsm4t(bf[q], bbase + (uint32_t)(q * 32));

            #pragma unroll
            for (int q = 0; q < 4; q++)
                #pragma unroll
                for (int h = 0; h < 2; h++) {
                    const int nt = q * 2 + h;
                    mma16(acc[0][nt], a[0], bf[q][h * 2], bf[q][h * 2 + 1]);
                    mma16(acc[1][nt], a[1], bf[q][h * 2], bf[q][h * 2 + 1]);
                }
        }

        __half* dst = (ch < 2) ? g_U : g_V;
        const bool isU = (ch < 2);
        #pragma unroll
        for (int mt = 0; mt < 2; mt++) {
            const int nd0 = n0 + wM * 32 + mt * 16 + g;
            #pragma unroll
            for (int nt = 0; nt < 8; nt++) {
                const int c = wN * 64 + nt * 8 + (t4 << 1);
                const int gc = (ch & 1) * 128 + c;
                const float bx = isU ? b1s[gc]     : 0.f;
                const float by = isU ? b1s[gc + 1] : 0.f;
                if (nd0 < n_nodes)
                    *(__half2*)(dst + (size_t)nd0 * HID + gc) =
                        __floats2half2_rn(acc[mt][nt][0] + bx, acc[mt][nt][1] + by);
                if (nd0 + 8 < n_nodes)
                    *(__half2*)(dst + (size_t)(nd0 + 8) * HID + gc) =
                        __floats2half2_rn(acc[mt][nt][2] + bx, acc[mt][nt][3] + by);
            }
        }
        __syncthreads();
        if (tid == 0 && ch + 2 < 4)
            bulk_in(sb + (uint32_t)(PWB_OFF + buf * 128 * PW_ST),
                    g_w1s + (size_t)(ch + 2) * 128 * 136, 128 * PW_ST,
                    sb + PMB_OFF + buf * 8);
    }
}

// ---------------- edge kernel: register A-frags, triple-buffered NC prefetch ----------
__global__ __launch_bounds__(512, 1)
void edge_kernel(const void*  __restrict__ ei_raw,
                 const float* __restrict__ b2,
                 float* __restrict__ out,
                 int E, int n_nodes)
{
    extern __shared__ char sm[];
    const uint32_t sb = smem_u32(sm);
    float* b2s = (float*)(sm + EB2_OFF);
    int*   sidx = (int*)(sm + ESI_OFF);

    const int tid  = threadIdx.x;
    const int lane = tid & 31;
    const int warp = tid >> 5;
    const int q    = lane & 3;
    const int e0   = blockIdx.x * E_BLK;
    const int nmax = (n_nodes < NMAX ? n_nodes : NMAX) - 1;

    const int bkrow = (lane & 7) + ((lane >> 3) & 1) * 8;
    const int bnoff = ((lane >> 4) & 1) * 16;

    if (tid == 0) {
        mbar_init(sb + EMB_OFF, 1);
        asm volatile("fence.proxy.async.shared::cta;" ::: "memory");
        bulk_in(sb + W2_OFF, g_w2s, 256 * W2_ST, sb + EMB_OFF);
        const int* e32 = (const int*)ei_raw;
        int hi0 = 1;
        #pragma unroll
        for (int k = 0; k < 16; k++) hi0 &= (e32[2 * k + 1] == 0);
        *(int*)(sm + EFL_OFF) = hi0;
    }
    __syncthreads();
    const bool is64 = (*(int*)(sm + EFL_OFF) != 0);

    if (tid < 2 * E_BLK) {
        int which = tid >= E_BLK;
        int r = tid - which * E_BLK;
        int e = e0 + r; if (e >= E) e = E - 1;
        long long v;
        if (is64) v = ((const long long*)ei_raw)[(size_t)which * E + e];
        else      v = ((const int*)ei_raw)[(size_t)which * E + e];
        int vi = (int)v;
        if (vi < 0) vi = 0;
        if (vi > nmax) vi = nmax;
        sidx[which * E_BLK + r] = vi;
    }
    if (tid < LAT) b2s[tid] = b2[tid];
    __syncthreads();

    const int rA = warp * 16 + (lane >> 2);
    const int rB = rA + 8;
    const int sA = sidx[rA], sB = sidx[rB];
    const int dA = sidx[E_BLK + rA], dB = sidx[E_BLK + rB];

    const __half* pUA = g_U + (size_t)sA * HID + q * 8;
    const __half* pUB = g_U + (size_t)sB * HID + q * 8;
    const __half* pVA = g_V + (size_t)dA * HID + q * 8;
    const __half* pVB = g_V + (size_t)dB * HID + q * 8;

    float acc[8][4];
    #pragma unroll
    for (int nt = 0; nt < 8; nt++)
        #pragma unroll
        for (int c = 0; c < 4; c++) acc[nt][c] = 0.f;

    // triple-buffered U/V registers (chunk = 32 k = 64 bytes), NC path
    uint4 uA[3], uB[3], vA[3], vB[3];
    #pragma unroll
    for (int c = 0; c < 2; c++) {
        const int off = c * 32;
        uA[c] = ldg_nc16(pUA + off);
        uB[c] = ldg_nc16(pUB + off);
        vA[c] = ldg_nc16(pVA + off);
        vB[c] = ldg_nc16(pVB + off);
    }

    mbar_wait(sb + EMB_OFF, 0);          // W2 resident

    #pragma unroll
    for (int c = 0; c < 8; c++) {
        const int buf = c % 3;
        if (c + 2 < 8) {
            const int off = (c + 2) * 32;
            const int nb = (c + 2) % 3;
            uA[nb] = ldg_nc16(pUA + off);
            uB[nb] = ldg_nc16(pUB + off);
            vA[nb] = ldg_nc16(pVA + off);
            vB[nb] = ldg_nc16(pVB + off);
        }
        uint32_t hA[4], hB[4];
        const uint32_t* ua = (const uint32_t*)&uA[buf];
        const uint32_t* ub = (const uint32_t*)&uB[buf];
        const uint32_t* va = (const uint32_t*)&vA[buf];
        const uint32_t* vb = (const uint32_t*)&vB[buf];
        #pragma unroll
        for (int r = 0; r < 4; r++) {
            hA[r] = relu2(ua[r], va[r]);
            hB[r] = relu2(ub[r], vb[r]);
        }
        #pragma unroll
        for (int j = 0; j < 2; j++) {
            uint32_t a[4] = { hA[j * 2], hB[j * 2], hA[j * 2 + 1], hB[j * 2 + 1] };
            const uint32_t bbase = sb + W2_OFF
                                 + (uint32_t)((c * 32 + j * 16 + bkrow) * W2_ST)
                                 + (uint32_t)bnoff;
            #pragma unroll
            for (int qq = 0; qq < 4; qq++) {
                uint32_t bf[4];
                ldsm4t(bf, bbase + (uint32_t)(qq * 32));
                mma16(acc[qq * 2 + 0], a, bf[0], bf[1]);
                mma16(acc[qq * 2 + 1], a, bf[2], bf[3]);
            }
        }
    }

    // epilogue: acc[nt][h] physical col = 16*(nt>>1) + 4q + 2*(nt&1) + h
    const int eA = e0 + rA;
    const int eB = e0 + rB;
    #pragma unroll
    for (int m = 0; m < 4; m++) {
        const int cbase = 16 * m + 4 * q;
        float4 bv = *(const float4*)(b2s + cbase);
        if (eA < E) {
            float4 o;
            o.x = acc[2 * m][0] + bv.x;     o.y = acc[2 * m][1] + bv.y;
            o.z = acc[2 * m + 1][0] + bv.z; o.w = acc[2 * m + 1][1] + bv.w;
            *(float4*)(out + (size_t)eA * LAT + cbase) = o;
        }
        if (eB < E) {
            float4 o;
            o.x = acc[2 * m][2] + bv.x;     o.y = acc[2 * m][3] + bv.y;
            o.z = acc[2 * m + 1][2] + bv.z; o.w = acc[2 * m + 1][3] + bv.w;
            *(float4*)(out + (size_t)eB * LAT + cbase) = o;
        }
    }
}

extern "C" void kernel_launch(void* const* d_in, const int* in_sizes, int n_in,
                              void* d_out, int out_size) {
    int ix = -1, ie = -1, iw1 = -1, ib1 = -1, iw2 = -1, ib2 = -1;
    for (int i = 0; i < n_in; i++) {
        switch (in_sizes[i]) {
            case 50000 * 128:  ix  = i; break;
            case 2 * 600000:   ie  = i; break;
            case 256 * 256:    iw1 = i; break;
            case 256:          ib1 = i; break;
            case 256 * 64:     iw2 = i; break;
            case 64:           ib2 = i; break;
            default: break;
        }
    }
    if (ix < 0)  ix = 0;
    if (ie < 0)  ie = 1;
    if (iw1 < 0) iw1 = 2;
    if (ib1 < 0) ib1 = 3;
    if (iw2 < 0) iw2 = 4;
    if (ib2 < 0) ib2 = 5;

    const float* x  = (const float*)d_in[ix];
    const void*  ei = (const void*)d_in[ie];
    const float* W1 = (const float*)d_in[iw1];
    const float* b1 = (const float*)d_in[ib1];
    const float* W2 = (const float*)d_in[iw2];
    const float* b2 = (const float*)d_in[ib2];
    float* out = (float*)d_out;

    const int E = in_sizes[ie] / 2;
    int n_nodes = in_sizes[ix] / DIN;
    if (n_nodes > NMAX) n_nodes = NMAX;

    prep_kernel<<<512, 256>>>(W1, W2);

    cudaFuncSetAttribute(node_kernel,
                         cudaFuncAttributeMaxDynamicSharedMemorySize, P_SMEM);
    node_kernel<<<(n_nodes + 127) / 128, 256, P_SMEM>>>(x, b1, n_nodes);

    cudaFuncSetAttribute(edge_kernel,
                         cudaFuncAttributeMaxDynamicSharedMemorySize, E_SMEM);
    edge_kernel<<<(E + E_BLK - 1) / E_BLK, 512, E_SMEM>>>(ei, b2, out, E, n_nodes);
}

// round 17
// speedup vs baseline: 2.1463x; 1.1209x over previous
#include <cuda_runtime.h>
#include <cuda_fp16.h>
#include <cstdint>

#define DIN   128
#define HID   256
#define LAT   64
#define NMAX  50000
#define E_BLK 512          // edges per edge-CTA (512 thr, 16 warps x 32 rows)

// ---------- static device buffers ----------
__device__ __align__(16) __half g_w1s[4 * 128 * 136];   // W1 staged [ch][k128][136]
__device__ __align__(16) __half g_w2s[256 * 72];        // W2 k-row + n-col permuted [256][72]
__device__ __align__(16) __half g_U  [NMAX * HID];      // x@W1a + b1
__device__ __align__(16) __half g_V  [NMAX * HID];      // x@W1b

// ---------- node kernel smem ----------
#define PA_ST   272
#define PAS_OFF 0
#define PWB_OFF (128 * PA_ST)
#define PW_ST   272
#define PB1_OFF (PWB_OFF + 2 * 128 * PW_ST)
#define PMB_OFF (PB1_OFF + 1024)
#define P_SMEM  105600

// ---------- edge kernel smem ----------
#define W2_OFF  0
#define W2_ST   144
#define EB2_OFF (256 * W2_ST)          // 36864 (64 f32)
#define ESI_OFF (EB2_OFF + 256)        // 37120 (1024 int)
#define EMB_OFF (ESI_OFF + 4096)       // 41216
#define EFL_OFF (EMB_OFF + 8)
#define E_SMEM  41472

// ---------------- helpers ----------------
__device__ __forceinline__ uint32_t smem_u32(const void* p) {
    uint32_t a;
    asm("{ .reg .u64 t; cvta.to.shared.u64 t, %1; cvt.u32.u64 %0, t; }" : "=r"(a) : "l"(p));
    return a;
}
__device__ __forceinline__ void mma16(float c[4], const uint32_t a[4],
                                      uint32_t b0, uint32_t b1) {
    asm volatile("mma.sync.aligned.m16n8k16.row.col.f32.f16.f16.f32 "
        "{%0,%1,%2,%3}, {%4,%5,%6,%7}, {%8,%9}, {%0,%1,%2,%3};"
        : "+f"(c[0]), "+f"(c[1]), "+f"(c[2]), "+f"(c[3])
        : "r"(a[0]), "r"(a[1]), "r"(a[2]), "r"(a[3]), "r"(b0), "r"(b1));
}
__device__ __forceinline__ void ldsm4(uint32_t r[4], uint32_t addr) {
    asm volatile("ldmatrix.sync.aligned.m8n8.x4.shared.b16 {%0,%1,%2,%3}, [%4];"
        : "=r"(r[0]), "=r"(r[1]), "=r"(r[2]), "=r"(r[3]) : "r"(addr));
}
__device__ __forceinline__ void ldsm4t(uint32_t r[4], uint32_t addr) {
    asm volatile("ldmatrix.sync.aligned.m8n8.x4.trans.shared.b16 {%0,%1,%2,%3}, [%4];"
        : "=r"(r[0]), "=r"(r[1]), "=r"(r[2]), "=r"(r[3]) : "r"(addr));
}
__device__ __forceinline__ void mbar_init(uint32_t a, uint32_t cnt) {
    asm volatile("mbarrier.init.shared.b64 [%0], %1;" :: "r"(a), "r"(cnt) : "memory");
}
__device__ __forceinline__ void mbar_wait(uint32_t a, uint32_t parity) {
    asm volatile(
        "{\n\t.reg .pred P;\n\t"
        "WL_%=:\n\t"
        "mbarrier.try_wait.parity.acquire.cta.shared::cta.b64 P, [%0], %1, 0x989680;\n\t"
        "@P bra.uni WD_%=;\n\t"
        "bra.uni WL_%=;\n\t"
        "WD_%=:\n\t}"
        :: "r"(a), "r"(parity) : "memory");
}
__device__ __forceinline__ void bulk_in(uint32_t dst, const void* src, uint32_t bytes,
                                        uint32_t mbar) {
    asm volatile("mbarrier.arrive.expect_tx.shared.b64 _, [%0], %1;"
                 :: "r"(mbar), "r"(bytes) : "memory");
    asm volatile("cp.async.bulk.shared::cta.global.mbarrier::complete_tx::bytes "
                 "[%0], [%1], %2, [%3];"
                 :: "r"(dst), "l"(src), "r"(bytes), "r"(mbar) : "memory");
}
__device__ __forceinline__ uint32_t relu2(uint32_t u, uint32_t v) {
    __half2 r = __hmax2(__hadd2(*(__half2*)&u, *(__half2*)&v), __float2half2_rn(0.f));
    return *(uint32_t*)&r;
}

// ---------------- prep: weights (W2 k-row + store-coalescing n-col permutation) ----
__global__ void prep_kernel(const float* __restrict__ W1,
                            const float* __restrict__ W2)
{
    const int stride = gridDim.x * blockDim.x;
    int gtid = blockIdx.x * blockDim.x + threadIdx.x;
    for (int i = gtid; i < 4 * 128 * 136; i += stride) {
        const int ch = i / (128 * 136);
        const int r  = i % (128 * 136);
        const int k  = r / 136;
        const int n  = r % 136;
        float val = 0.f;
        if (n < 128)
            val = W1[(size_t)((ch < 2 ? 0 : 128) + k) * HID + (ch & 1) * 128 + n];
        g_w1s[i] = __float2half_rn(val);
    }
    for (int i = gtid; i < 256 * 72; i += stride) {
        const int r = i / 72, m = i % 72;
        float val = 0.f;
        if (m < 64) {
            const int c   = r >> 5;
            const int rem = r & 31;
            const int j   = rem >> 4;
            const int l   = rem & 15;
            const int q   = (l & 7) >> 1;
            const int dlt = l & 1;
            const int hi  = l >> 3;
            const int p   = 32 * c + 8 * q + 4 * j + 2 * hi + dlt;       // physical k row
            const int srcc = 16 * (m >> 4) + 4 * ((m & 7) >> 1)
                           + 2 * ((m >> 3) & 1) + (m & 1);               // physical col
            val = W2[(size_t)p * LAT + srcc];
        }
        g_w2s[i] = __float2half_rn(val);
    }
}

// ---------------- node kernel: U = x@W1a + b1, V = x@W1b ----------------
__global__ __launch_bounds__(256, 2)
void node_kernel(const float* __restrict__ x,
                 const float* __restrict__ b1, int n_nodes)
{
    extern __shared__ char sm[];
    const uint32_t sb = smem_u32(sm);
    float* b1s = (float*)(sm + PB1_OFF);

    const int tid  = threadIdx.x;
    const int lane = tid & 31;
    const int warp = tid >> 5;
    const int wM   = warp & 3;
    const int wN   = warp >> 2;
    const int g    = lane >> 2;
    const int t4   = lane & 3;
    const int n0   = blockIdx.x * 128;

    const int lrow  = lane & 15;
    const int lkoff = (lane >> 4) * 16;
    const int bkrow = (lane & 7) + ((lane >> 3) & 1) * 8;
    const int bnoff = ((lane >> 4) & 1) * 16;

    if (tid == 0) {
        mbar_init(sb + PMB_OFF, 1);
        mbar_init(sb + PMB_OFF + 8, 1);
        asm volatile("fence.proxy.async.shared::cta;" ::: "memory");
        bulk_in(sb + PWB_OFF,               g_w1s,             128 * PW_ST, sb + PMB_OFF);
        bulk_in(sb + PWB_OFF + 128 * PW_ST, g_w1s + 128 * 136, 128 * PW_ST, sb + PMB_OFF + 8);
    }
    b1s[tid] = b1[tid];

    #pragma unroll
    for (int j = 0; j < 16; j++) {
        int i = tid + j * 256;
        int r = i >> 5;
        int ch = i & 31;
        int node = n0 + r; if (node >= n_nodes) node = n_nodes - 1;
        float4 v = *(const float4*)(x + (size_t)node * DIN + ch * 4);
        __half2 h0 = __floats2half2_rn(v.x, v.y);
        __half2 h1 = __floats2half2_rn(v.z, v.w);
        uint2 u;
        u.x = *(uint32_t*)&h0;
        u.y = *(uint32_t*)&h1;
        *(uint2*)(sm + PAS_OFF + r * PA_ST + ch * 8) = u;
    }
    __syncthreads();

    #pragma unroll 1
    for (int ch = 0; ch < 4; ch++) {
        const int buf = ch & 1;
        mbar_wait(sb + PMB_OFF + buf * 8, (uint32_t)((ch >> 1) & 1));
        const uint32_t wb = sb + (uint32_t)(PWB_OFF + buf * 128 * PW_ST);

        float acc[2][8][4];
        #pragma unroll
        for (int mt = 0; mt < 2; mt++)
            #pragma unroll
            for (int nt = 0; nt < 8; nt++)
                #pragma unroll
                for (int q = 0; q < 4; q++) acc[mt][nt][q] = 0.f;

        #pragma unroll
        for (int kk = 0; kk < 8; kk++) {
            const int kh = kk * 16;
            uint32_t a[2][4];
            const uint32_t abase = sb + PAS_OFF + (uint32_t)((wM * 32 + lrow) * PA_ST)
                                 + (uint32_t)(kh * 2 + lkoff);
            ldsm4(a[0], abase);
            ldsm4(a[1], abase + (uint32_t)(16 * PA_ST));

            uint32_t bf[4][4];
            const uint32_t bbase = wb + (uint32_t)((kh + bkrow) * PW_ST)
                                 + (uint32_t)(wN * 128 + bnoff);
            #pragma unroll
            for (int q = 0; q < 4; q++) ldsm4t(bf[q], bbase + (uint32_t)(q * 32));

            #pragma unroll
            for (int q = 0; q < 4; q++)
                #pragma unroll
                for (int h = 0; h < 2; h++) {
                    const int nt = q * 2 + h;
                    mma16(acc[0][nt], a[0], bf[q][h * 2], bf[q][h * 2 + 1]);
                    mma16(acc[1][nt], a[1], bf[q][h * 2], bf[q][h * 2 + 1]);
                }
        }

        __half* dst = (ch < 2) ? g_U : g_V;
        const bool isU = (ch < 2);
        #pragma unroll
        for (int mt = 0; mt < 2; mt++) {
            const int nd0 = n0 + wM * 32 + mt * 16 + g;
            #pragma unroll
            for (int nt = 0; nt < 8; nt++) {
                const int c = wN * 64 + nt * 8 + (t4 << 1);
                const int gc = (ch & 1) * 128 + c;
                const float bx = isU ? b1s[gc]     : 0.f;
                const float by = isU ? b1s[gc + 1] : 0.f;
                if (nd0 < n_nodes)
                    *(__half2*)(dst + (size_t)nd0 * HID + gc) =
                        __floats2half2_rn(acc[mt][nt][0] + bx, acc[mt][nt][1] + by);
                if (nd0 + 8 < n_nodes)
                    *(__half2*)(dst + (size_t)(nd0 + 8) * HID + gc) =
                        __floats2half2_rn(acc[mt][nt][2] + bx, acc[mt][nt][3] + by);
            }
        }
        __syncthreads();
        if (tid == 0 && ch + 2 < 4)
            bulk_in(sb + (uint32_t)(PWB_OFF + buf * 128 * PW_ST),
                    g_w1s + (size_t)(ch + 2) * 128 * 136, 128 * PW_ST,
                    sb + PMB_OFF + buf * 8);
    }
}

// ---------------- edge kernel: M=32/warp, register A-frags, j-split pipeline ----------
__global__ __launch_bounds__(512, 1)
void edge_kernel(const void*  __restrict__ ei_raw,
                 const float* __restrict__ b2,
                 float* __restrict__ out,
                 int E, int n_nodes)
{
    extern __shared__ char sm[];
    const uint32_t sb = smem_u32(sm);
    float* b2s = (float*)(sm + EB2_OFF);
    int*   sidx = (int*)(sm + ESI_OFF);

    const int tid  = threadIdx.x;
    const int lane = tid & 31;
    const int warp = tid >> 5;            // 16 warps x 32 edge rows
    const int q    = lane & 3;
    const int lr   = lane >> 2;           // 0..7
    const int e0   = blockIdx.x * E_BLK;
    const int nmax = (n_nodes < NMAX ? n_nodes : NMAX) - 1;

    const int bkrow = (lane & 7) + ((lane >> 3) & 1) * 8;
    const int bnoff = ((lane >> 4) & 1) * 16;

    if (tid == 0) {
        mbar_init(sb + EMB_OFF, 1);
        asm volatile("fence.proxy.async.shared::cta;" ::: "memory");
        bulk_in(sb + W2_OFF, g_w2s, 256 * W2_ST, sb + EMB_OFF);
        const int* e32 = (const int*)ei_raw;
        int hi0 = 1;
        #pragma unroll
        for (int k = 0; k < 16; k++) hi0 &= (e32[2 * k + 1] == 0);
        *(int*)(sm + EFL_OFF) = hi0;
    }
    __syncthreads();
    const bool is64 = (*(int*)(sm + EFL_OFF) != 0);

    #pragma unroll
    for (int t = tid; t < 2 * E_BLK; t += 512) {
        int which = t >= E_BLK;
        int r = t - which * E_BLK;
        int e = e0 + r; if (e >= E) e = E - 1;
        long long v;
        if (is64) v = ((const long long*)ei_raw)[(size_t)which * E + e];
        else      v = ((const int*)ei_raw)[(size_t)which * E + e];
        int vi = (int)v;
        if (vi < 0) vi = 0;
        if (vi > nmax) vi = nmax;
        sidx[which * E_BLK + r] = vi;
    }
    if (tid < LAT) b2s[tid] = b2[tid];
    __syncthreads();

    // this thread's 4 edge rows: base + lr + {0,8,16,24}
    const int base = warp * 32;
    const __half* pU[4];
    const __half* pV[4];
    #pragma unroll
    for (int i = 0; i < 4; i++) {
        const int r = base + lr + i * 8;
        pU[i] = g_U + (size_t)sidx[r] * HID + q * 8;
        pV[i] = g_V + (size_t)sidx[E_BLK + r] * HID + q * 8;
    }

    float acc[2][8][4];
    #pragma unroll
    for (int mt = 0; mt < 2; mt++)
        #pragma unroll
        for (int nt = 0; nt < 8; nt++)
            #pragma unroll
            for (int c = 0; c < 4; c++) acc[mt][nt][c] = 0.f;

    // j-split gather registers: u0/v0 = first 4 halves (j=0), u1/v1 = next 4 (j=1)
    uint2 u0[4], u1[4], v0[4], v1[4];
    #pragma unroll
    for (int i = 0; i < 4; i++) {
        u0[i] = *(const uint2*)(pU[i]);
        u1[i] = *(const uint2*)(pU[i] + 4);
        v0[i] = *(const uint2*)(pV[i]);
        v1[i] = *(const uint2*)(pV[i] + 4);
    }

    mbar_wait(sb + EMB_OFF, 0);           // W2 resident

    #pragma unroll
    for (int c = 0; c < 8; c++) {
        // ---- j = 0 half ----
        {
            uint32_t hx[4], hy[4];
            #pragma unroll
            for (int i = 0; i < 4; i++) {
                hx[i] = relu2(u0[i].x, v0[i].x);
                hy[i] = relu2(u0[i].y, v0[i].y);
            }
            if (c < 7) {
                const int off = (c + 1) * 32;
                #pragma unroll
                for (int i = 0; i < 4; i++) {
                    u0[i] = *(const uint2*)(pU[i] + off);
                    v0[i] = *(const uint2*)(pV[i] + off);
                }
            }
            uint32_t a0[4] = { hx[0], hx[1], hy[0], hy[1] };   // rows lr, lr+8
            uint32_t a1[4] = { hx[2], hx[3], hy[2], hy[3] };   // rows lr+16, lr+24
            const uint32_t bbase = sb + W2_OFF
                                 + (uint32_t)((c * 32 + bkrow) * W2_ST)
                                 + (uint32_t)bnoff;
            #pragma unroll
            for (int qq = 0; qq < 4; qq++) {
                uint32_t bf[4];
                ldsm4t(bf, bbase + (uint32_t)(qq * 32));
                mma16(acc[0][qq * 2 + 0], a0, bf[0], bf[1]);
                mma16(acc[0][qq * 2 + 1], a0, bf[2], bf[3]);
                mma16(acc[1][qq * 2 + 0], a1, bf[0], bf[1]);
                mma16(acc[1][qq * 2 + 1], a1, bf[2], bf[3]);
            }
        }
        // ---- j = 1 half ----
        {
            uint32_t hx[4], hy[4];
            #pragma unroll
            for (int i = 0; i < 4; i++) {
                hx[i] = relu2(u1[i].x, v1[i].x);
                hy[i] = relu2(u1[i].y, v1[i].y);
            }
            if (c < 7) {
                const int off = (c + 1) * 32 + 4;
                #pragma unroll
                for (int i = 0; i < 4; i++) {
                    u1[i] = *(const uint2*)(pU[i] + off);
                    v1[i] = *(const uint2*)(pV[i] + off);
                }
            }
            uint32_t a0[4] = { hx[0], hx[1], hy[0], hy[1] };
            uint32_t a1[4] = { hx[2], hx[3], hy[2], hy[3] };
            const uint32_t bbase = sb + W2_OFF
                                 + (uint32_t)((c * 32 + 16 + bkrow) * W2_ST)
                                 + (uint32_t)bnoff;
            #pragma unroll
            for (int qq = 0; qq < 4; qq++) {
                uint32_t bf[4];
                ldsm4t(bf, bbase + (uint32_t)(qq * 32));
                mma16(acc[0][qq * 2 + 0], a0, bf[0], bf[1]);
                mma16(acc[0][qq * 2 + 1], a0, bf[2], bf[3]);
                mma16(acc[1][qq * 2 + 0], a1, bf[0], bf[1]);
                mma16(acc[1][qq * 2 + 1], a1, bf[2], bf[3]);
            }
        }
    }

    // epilogue: per mt tile, acc[mt][nt][h] col = 16*(nt>>1) + 4q + 2*(nt&1) + h
    #pragma unroll
    for (int mt = 0; mt < 2; mt++) {
        const int eA = e0 + base + mt * 16 + lr;
        const int eB = eA + 8;
        #pragma unroll
        for (int m = 0; m < 4; m++) {
            const int cbase = 16 * m + 4 * q;
            float4 bv = *(const float4*)(b2s + cbase);
            if (eA < E) {
                float4 o;
                o.x = acc[mt][2 * m][0] + bv.x;     o.y = acc[mt][2 * m][1] + bv.y;
                o.z = acc[mt][2 * m + 1][0] + bv.z; o.w = acc[mt][2 * m + 1][1] + bv.w;
                *(float4*)(out + (size_t)eA * LAT + cbase) = o;
            }
            if (eB < E) {
                float4 o;
                o.x = acc[mt][2 * m][2] + bv.x;     o.y = acc[mt][2 * m][3] + bv.y;
                o.z = acc[mt][2 * m + 1][2] + bv.z; o.w = acc[mt][2 * m + 1][3] + bv.w;
                *(float4*)(out + (size_t)eB * LAT + cbase) = o;
            }
        }
    }
}

extern "C" void kernel_launch(void* const* d_in, const int* in_sizes, int n_in,
                              void* d_out, int out_size) {
    int ix = -1, ie = -1, iw1 = -1, ib1 = -1, iw2 = -1, ib2 = -1;
    for (int i = 0; i < n_in; i++) {
        switch (in_sizes[i]) {
            case 50000 * 128:  ix  = i; break;
            case 2 * 600000:   ie  = i; break;
            case 256 * 256:    iw1 = i; break;
            case 256:          ib1 = i; break;
            case 256 * 64:     iw2 = i; break;
            case 64:           ib2 = i; break;
            default: break;
        }
    }
    if (ix < 0)  ix = 0;
    if (ie < 0)  ie = 1;
    if (iw1 < 0) iw1 = 2;
    if (ib1 < 0) ib1 = 3;
    if (iw2 < 0) iw2 = 4;
    if (ib2 < 0) ib2 = 5;

    const float* x  = (const float*)d_in[ix];
    const void*  ei = (const void*)d_in[ie];
    const float* W1 = (const float*)d_in[iw1];
    const float* b1 = (const float*)d_in[ib1];
    const float* W2 = (const float*)d_in[iw2];
    const float* b2 = (const float*)d_in[ib2];
    float* out = (float*)d_out;

    const int E = in_sizes[ie] / 2;
    int n_nodes = in_sizes[ix] / DIN;
    if (n_nodes > NMAX) n_nodes = NMAX;

    prep_kernel<<<512, 256>>>(W1, W2);

    cudaFuncSetAttribute(node_kernel,
                         cudaFuncAttributeMaxDynamicSharedMemorySize, P_SMEM);
    node_kernel<<<(n_nodes + 127) / 128, 256, P_SMEM>>>(x, b1, n_nodes);

    cudaFuncSetAttribute(edge_kernel,
                         cudaFuncAttributeMaxDynamicSharedMemorySize, E_SMEM);
    edge_kernel<<<(E + E_BLK - 1) / E_BLK, 512, E_SMEM>>>(ei, b2, out, E, n_nodes);
}